// round 1
// baseline (speedup 1.0000x reference)
#include <cuda_runtime.h>

#define T_STEPS 2000
#define HID 51
#define G4 204      // 4*HID gate rows
#define FEAT 49     // 7*7

__device__ __forceinline__ float sigm(float x) {
    return __fdividef(1.0f, 1.0f + __expf(-x));
}
__device__ __forceinline__ float ftanh(float x) {
    return __fdividef(2.0f, 1.0f + __expf(-2.0f * x)) - 1.0f;
}

__global__ __launch_bounds__(256, 1)
void lstm_seq_kernel(const float* __restrict__ stim,
                     const float* __restrict__ Wl,   const float* __restrict__ bl,
                     const float* __restrict__ Wih1, const float* __restrict__ Whh1,
                     const float* __restrict__ bih1, const float* __restrict__ bhh1,
                     const float* __restrict__ Wih2, const float* __restrict__ Whh2,
                     const float* __restrict__ bih2, const float* __restrict__ bhh2,
                     const float* __restrict__ Wa,   const float* __restrict__ ba,
                     float* __restrict__ out)
{
    __shared__ float xlin[T_STEPS];      // 8000 B
    __shared__ float h1_sh[HID + 1];
    __shared__ float act_sh[G4];
    __shared__ float wl_sh[FEAT];

    const int tid  = threadIdx.x;
    const int lane = tid & 31;
    const int wid  = tid >> 5;
    const int n    = blockIdx.x;

    if (tid < FEAT)    wl_sh[tid] = Wl[tid];
    if (tid < HID + 1) h1_sh[tid] = 0.0f;
    __syncthreads();

    // ---------------- Phase 0: x_lin = relu(stim . Wl + bl), warp-per-timestep ----
    {
        const float blv = bl[0];
        const float* sb = stim + (size_t)n * T_STEPS * FEAT;
        for (int t = wid; t < T_STEPS; t += 8) {
            const float* p = sb + t * FEAT;
            float s = 0.0f;
            if (lane < FEAT)      s  = p[lane]      * wl_sh[lane];
            if (lane + 32 < FEAT) s += p[lane + 32] * wl_sh[lane + 32];
            #pragma unroll
            for (int off = 16; off; off >>= 1)
                s += __shfl_xor_sync(0xffffffffu, s, off);
            if (lane == 0) xlin[t] = fmaxf(s + blv, 0.0f);
        }
    }

    // ---------------- Per-thread static weights ----------------
    // Gate threads 0..203: Whh1 row in registers.
    float w[HID];
    float wih = 0.0f, bias = 0.0f;
    int   sel = 0;
    if (tid < G4) {
        #pragma unroll
        for (int j = 0; j < HID; j++) w[j] = Whh1[tid * HID + j];
        wih  = Wih1[tid];
        bias = bih1[tid] + bhh1[tid];
        sel  = tid / HID;                 // 0:i 1:f 2:g 3:o
    }

    // Warp 7: LSTM2 weights (4 rows of 51, 2 elems per lane per row).
    float w2a[4], w2b[4], b2[4], whh2r[4];
    float h2 = 0.0f, c2 = 0.0f, wav = 0.0f, bav = 0.0f;
    if (wid == 7) {
        #pragma unroll
        for (int k = 0; k < 4; k++) {
            w2a[k]   = Wih2[k * HID + lane];
            w2b[k]   = (lane + 32 < HID) ? Wih2[k * HID + lane + 32] : 0.0f;
            b2[k]    = bih2[k] + bhh2[k];
            whh2r[k] = Whh2[k];
        }
        wav = Wa[0];
        bav = ba[0];
    }

    float c1 = 0.0f;
    float* outp = out + (size_t)n * T_STEPS;
    __syncthreads();

    // ---------------- Recurrence: T+1 iterations ----------------
    // Iter t: gate threads compute gates(t) (needs h1(t-1));
    //         warp 7 concurrently computes LSTM2/output for step t-1 (needs h1(t-1)).
    for (int t = 0; t <= T_STEPS; t++) {
        if (tid < G4) {
            if (t < T_STEPS) {
                float x  = xlin[t];
                float a0 = bias + x * wih;
                float a1 = 0.0f, a2 = 0.0f, a3 = 0.0f;
                #pragma unroll
                for (int j = 0; j < 48; j += 4) {
                    a0 += h1_sh[j]     * w[j];
                    a1 += h1_sh[j + 1] * w[j + 1];
                    a2 += h1_sh[j + 2] * w[j + 2];
                    a3 += h1_sh[j + 3] * w[j + 3];
                }
                a0 += h1_sh[48] * w[48];
                a1 += h1_sh[49] * w[49];
                a2 += h1_sh[50] * w[50];
                float acc = (a0 + a1) + (a2 + a3);
                act_sh[tid] = (sel == 2) ? ftanh(acc) : sigm(acc);
            }
        } else if (wid == 7 && t > 0) {
            // LSTM2 for step t-1, using h1_sh = h1(t-1)
            float h1a = h1_sh[lane];
            float h1b = (lane + 32 < HID) ? h1_sh[lane + 32] : 0.0f;
            float p0 = h1a * w2a[0] + h1b * w2b[0];
            float p1 = h1a * w2a[1] + h1b * w2b[1];
            float p2 = h1a * w2a[2] + h1b * w2b[2];
            float p3 = h1a * w2a[3] + h1b * w2b[3];
            #pragma unroll
            for (int off = 16; off; off >>= 1) {
                p0 += __shfl_xor_sync(0xffffffffu, p0, off);
                p1 += __shfl_xor_sync(0xffffffffu, p1, off);
                p2 += __shfl_xor_sync(0xffffffffu, p2, off);
                p3 += __shfl_xor_sync(0xffffffffu, p3, off);
            }
            // all lanes hold identical sums; compute redundantly (keeps h2/c2 uniform)
            float gi = sigm (p0 + b2[0] + h2 * whh2r[0]);
            float gf = sigm (p1 + b2[1] + h2 * whh2r[1]);
            float gg = ftanh(p2 + b2[2] + h2 * whh2r[2]);
            float go = sigm (p3 + b2[3] + h2 * whh2r[3]);
            c2 = gf * c2 + gi * gg;
            h2 = go * ftanh(c2);
            if (lane == 0) outp[t - 1] = h2 * wav + bav;
        }
        __syncthreads();

        if (t < T_STEPS && tid < HID) {
            float gi = act_sh[tid];
            float gf = act_sh[HID + tid];
            float gg = act_sh[2 * HID + tid];
            float go = act_sh[3 * HID + tid];
            c1 = gf * c1 + gi * gg;
            h1_sh[tid] = go * ftanh(c1);
        }
        __syncthreads();
    }
}

extern "C" void kernel_launch(void* const* d_in, const int* in_sizes, int n_in,
                              void* d_out, int out_size) {
    const float* stim = (const float*)d_in[0];
    const float* Wl   = (const float*)d_in[1];
    const float* bl   = (const float*)d_in[2];
    const float* Wih1 = (const float*)d_in[3];
    const float* Whh1 = (const float*)d_in[4];
    const float* bih1 = (const float*)d_in[5];
    const float* bhh1 = (const float*)d_in[6];
    const float* Wih2 = (const float*)d_in[7];
    const float* Whh2 = (const float*)d_in[8];
    const float* bih2 = (const float*)d_in[9];
    const float* bhh2 = (const float*)d_in[10];
    const float* Wa   = (const float*)d_in[11];
    const float* ba   = (const float*)d_in[12];

    const int N = out_size / T_STEPS;   // 256
    lstm_seq_kernel<<<N, 256>>>(stim, Wl, bl, Wih1, Whh1, bih1, bhh1,
                                Wih2, Whh2, bih2, bhh2, Wa, ba,
                                (float*)d_out);
}

// round 3
// speedup vs baseline: 1.6421x; 1.6421x over previous
#include <cuda_runtime.h>

#define T_STEPS 2000
#define HID 51
#define G4 204      // 4*HID gate rows
#define FEAT 49     // 7*7

typedef unsigned long long ull;

__device__ __forceinline__ float sigm(float x) {
    return __fdividef(1.0f, 1.0f + __expf(-x));
}
__device__ __forceinline__ float ftanh(float x) {
    return __fdividef(2.0f, 1.0f + __expf(-2.0f * x)) - 1.0f;
}

__device__ __forceinline__ ull pk(float a, float b) {
    ull r;
    asm("mov.b64 %0, {%1, %2};" : "=l"(r) : "f"(a), "f"(b));
    return r;
}
__device__ __forceinline__ ull fma2(ull a, ull b, ull c) {
    ull d;
    asm("fma.rn.f32x2 %0, %1, %2, %3;" : "=l"(d) : "l"(a), "l"(b), "l"(c));
    return d;
}
__device__ __forceinline__ ull add2(ull a, ull b) {
    ull d;
    asm("add.rn.f32x2 %0, %1, %2;" : "=l"(d) : "l"(a), "l"(b));
    return d;
}
__device__ __forceinline__ void upk(ull v, float& a, float& b) {
    asm("mov.b64 {%0, %1}, %2;" : "=f"(a), "=f"(b) : "l"(v));
}

__global__ __launch_bounds__(256, 2)
void lstm_seq_kernel(const float* __restrict__ stim,
                     const float* __restrict__ Wl,   const float* __restrict__ bl,
                     const float* __restrict__ Wih1, const float* __restrict__ Whh1,
                     const float* __restrict__ bih1, const float* __restrict__ bhh1,
                     const float* __restrict__ Wih2, const float* __restrict__ Whh2,
                     const float* __restrict__ bih2, const float* __restrict__ bhh2,
                     const float* __restrict__ Wa,   const float* __restrict__ ba,
                     float* __restrict__ out)
{
    __shared__ float xlin[T_STEPS];                    // 8000 B
    __shared__ __align__(16) float h1_sh[52];          // [51] stays 0 (pad)
    __shared__ float act_sh[G4];
    __shared__ float wl_sh[FEAT];

    const int tid  = threadIdx.x;
    const int lane = tid & 31;
    const int wid  = tid >> 5;
    const int n    = blockIdx.x;

    if (tid < FEAT) wl_sh[tid] = Wl[tid];
    if (tid < 52)   h1_sh[tid] = 0.0f;
    __syncthreads();

    // ---- Phase 0: x_lin = relu(stim . Wl + bl), warp-per-timestep ----
    {
        const float blv = bl[0];
        const float* sb = stim + (size_t)n * T_STEPS * FEAT;
        for (int t = wid; t < T_STEPS; t += 8) {
            const float* p = sb + t * FEAT;
            float s = 0.0f;
            if (lane < FEAT)      s  = p[lane]      * wl_sh[lane];
            if (lane + 32 < FEAT) s += p[lane + 32] * wl_sh[lane + 32];
            #pragma unroll
            for (int off = 16; off; off >>= 1)
                s += __shfl_xor_sync(0xffffffffu, s, off);
            if (lane == 0) xlin[t] = fmaxf(s + blv, 0.0f);
        }
    }

    // ---- Per-thread static weights ----
    // Gate threads 0..203: Whh1 row packed into 26 f32x2 registers.
    ull   wp[26];
    float wih = 0.0f, bias = 0.0f;
    int   sel = 0;
    if (tid < G4) {
        const float* wr = Whh1 + tid * HID;
        #pragma unroll
        for (int j = 0; j < 25; j++) wp[j] = pk(wr[2 * j], wr[2 * j + 1]);
        wp[25] = pk(wr[50], 0.0f);
        wih  = Wih1[tid];
        bias = bih1[tid] + bhh1[tid];
        sel  = tid / HID;                 // 0:i 1:f 2:g 3:o
    }

    // Warp 7: LSTM2 weights (4 rows of 51, 2 elems per lane per row).
    float w2a[4], w2b[4], b2[4], whh2r[4];
    float h2 = 0.0f, c2 = 0.0f, wav = 0.0f, bav = 0.0f;
    if (wid == 7) {
        #pragma unroll
        for (int k = 0; k < 4; k++) {
            w2a[k]   = Wih2[k * HID + lane];
            w2b[k]   = (lane + 32 < HID) ? Wih2[k * HID + lane + 32] : 0.0f;
            b2[k]    = bih2[k] + bhh2[k];
            whh2r[k] = Whh2[k];
        }
        wav = Wa[0];
        bav = ba[0];
    }

    float c1 = 0.0f;
    float* outp = out + (size_t)n * T_STEPS;
    __syncthreads();

    const float4* h4 = reinterpret_cast<const float4*>(h1_sh);

    // ---- Recurrence: T+1 iterations ----
    // Iter t: gate threads compute gates(t) (needs h1(t-1));
    //         warp 7 concurrently computes LSTM2/output for step t-1.
    for (int t = 0; t <= T_STEPS; t++) {
        if (tid < G4) {
            if (t < T_STEPS) {
                float x = xlin[t];
                ull a0 = pk(0.0f, 0.0f), a1 = a0, a2 = a0, a3 = a0;
                #pragma unroll
                for (int q = 0; q < 13; q += 2) {
                    float4 hv = h4[q];
                    a0 = fma2(pk(hv.x, hv.y), wp[2 * q],     a0);
                    a1 = fma2(pk(hv.z, hv.w), wp[2 * q + 1], a1);
                    if (q + 1 < 13) {
                        float4 hw = h4[q + 1];
                        a2 = fma2(pk(hw.x, hw.y), wp[2 * q + 2], a2);
                        a3 = fma2(pk(hw.z, hw.w), wp[2 * q + 3], a3);
                    }
                }
                a0 = add2(a0, a1);
                a2 = add2(a2, a3);
                a0 = add2(a0, a2);
                float lo, hi;
                upk(a0, lo, hi);
                float acc = (lo + hi) + (bias + x * wih);
                act_sh[tid] = (sel == 2) ? ftanh(acc) : sigm(acc);
            }
        } else if (wid == 7 && t > 0) {
            // LSTM2 for step t-1, using h1_sh = h1(t-1)
            float h1a = h1_sh[lane];
            float h1b = (lane + 32 < HID) ? h1_sh[lane + 32] : 0.0f;
            float p0 = h1a * w2a[0] + h1b * w2b[0];
            float p1 = h1a * w2a[1] + h1b * w2b[1];
            float p2 = h1a * w2a[2] + h1b * w2b[2];
            float p3 = h1a * w2a[3] + h1b * w2b[3];
            #pragma unroll
            for (int off = 16; off; off >>= 1) {
                p0 += __shfl_xor_sync(0xffffffffu, p0, off);
                p1 += __shfl_xor_sync(0xffffffffu, p1, off);
                p2 += __shfl_xor_sync(0xffffffffu, p2, off);
                p3 += __shfl_xor_sync(0xffffffffu, p3, off);
            }
            float gi = sigm (p0 + b2[0] + h2 * whh2r[0]);
            float gf = sigm (p1 + b2[1] + h2 * whh2r[1]);
            float gg = ftanh(p2 + b2[2] + h2 * whh2r[2]);
            float go = sigm (p3 + b2[3] + h2 * whh2r[3]);
            c2 = gf * c2 + gi * gg;
            h2 = go * ftanh(c2);
            if (lane == 0) outp[t - 1] = h2 * wav + bav;
        }
        __syncthreads();

        if (t < T_STEPS && tid < HID) {
            float gi = act_sh[tid];
            float gf = act_sh[HID + tid];
            float gg = act_sh[2 * HID + tid];
            float go = act_sh[3 * HID + tid];
            c1 = gf * c1 + gi * gg;
            h1_sh[tid] = go * ftanh(c1);
        }
        __syncthreads();
    }
}

extern "C" void kernel_launch(void* const* d_in, const int* in_sizes, int n_in,
                              void* d_out, int out_size) {
    const float* stim = (const float*)d_in[0];
    const float* Wl   = (const float*)d_in[1];
    const float* bl   = (const float*)d_in[2];
    const float* Wih1 = (const float*)d_in[3];
    const float* Whh1 = (const float*)d_in[4];
    const float* bih1 = (const float*)d_in[5];
    const float* bhh1 = (const float*)d_in[6];
    const float* Wih2 = (const float*)d_in[7];
    const float* Whh2 = (const float*)d_in[8];
    const float* bih2 = (const float*)d_in[9];
    const float* bhh2 = (const float*)d_in[10];
    const float* Wa   = (const float*)d_in[11];
    const float* ba   = (const float*)d_in[12];

    const int N = out_size / T_STEPS;   // 256
    lstm_seq_kernel<<<N, 256>>>(stim, Wl, bl, Wih1, Whh1, bih1, bhh1,
                                Wih2, Whh2, bih2, bhh2, Wa, ba,
                                (float*)d_out);
}